// round 1
// baseline (speedup 1.0000x reference)
#include <cuda_runtime.h>
#include <cuda_bf16.h>
#include <cstdint>

#define N_NODES 100000
#define N_EDGES 1600000
#define IN_DIM  128
#define OUT_DIM 64

// Scratch for xw = x@W + b  (allocation-free rule: __device__ global)
__device__ float g_xw[(size_t)N_NODES * OUT_DIM];

// ---------------------------------------------------------------------------
// Zero-init d_out (it is poisoned before timing; atomics need zeros)
// ---------------------------------------------------------------------------
__global__ void zero_kernel(float4* __restrict__ out) {
    int i = blockIdx.x * blockDim.x + threadIdx.x;
    if (i < (N_NODES * OUT_DIM) / 4) {
        out[i] = make_float4(0.f, 0.f, 0.f, 0.f);
    }
}

// ---------------------------------------------------------------------------
// Linear: xw[n, :] = x[n, :] @ W + b
// One node per thread. W (128x64 = 32KB) staged in smem, broadcast-read.
// Accumulators held as 32 packed f32x2 pairs; fma.rn.f32x2 doubles FMA rate.
// ---------------------------------------------------------------------------
__global__ __launch_bounds__(256) void linear_kernel(
    const float* __restrict__ x,
    const float* __restrict__ W,
    const float* __restrict__ b,
    float* __restrict__ xw)
{
    __shared__ float Ws[IN_DIM * OUT_DIM];
    __shared__ float bs[OUT_DIM];

    int tid = threadIdx.x;
    // cooperative load of W (2048 float4)
    const float4* W4  = (const float4*)W;
    float4*       Ws4 = (float4*)Ws;
    #pragma unroll
    for (int i = tid; i < (IN_DIM * OUT_DIM) / 4; i += 256) Ws4[i] = W4[i];
    if (tid < OUT_DIM) bs[tid] = b[tid];
    __syncthreads();

    int n = blockIdx.x * 256 + tid;
    if (n >= N_NODES) return;

    // acc[p] holds outputs (2p, 2p+1) packed as f32x2
    unsigned long long acc[OUT_DIM / 2];
    #pragma unroll
    for (int p = 0; p < OUT_DIM / 2; p++) {
        asm("mov.b64 %0, {%1, %2};" : "=l"(acc[p]) : "f"(bs[2 * p]), "f"(bs[2 * p + 1]));
    }

    const float4* xr = (const float4*)(x + (size_t)n * IN_DIM);
    const ulonglong2* Ws2 = (const ulonglong2*)Ws;   // 2 packed pairs per 16B

    #pragma unroll 2
    for (int k4 = 0; k4 < IN_DIM / 4; k4++) {
        float4 xv = xr[k4];
        #pragma unroll
        for (int j = 0; j < 4; j++) {
            float xk = (j == 0) ? xv.x : (j == 1) ? xv.y : (j == 2) ? xv.z : xv.w;
            unsigned long long xx;
            asm("mov.b64 %0, {%1, %1};" : "=l"(xx) : "f"(xk));
            int k = k4 * 4 + j;
            const ulonglong2* wr = Ws2 + (size_t)k * (OUT_DIM / 4); // 16 x 16B per row
            #pragma unroll
            for (int q = 0; q < OUT_DIM / 4; q++) {
                ulonglong2 wv = wr[q];   // LDS.128 broadcast (uniform across warp)
                asm("fma.rn.f32x2 %0, %1, %2, %0;" : "+l"(acc[2 * q])     : "l"(xx), "l"(wv.x));
                asm("fma.rn.f32x2 %0, %1, %2, %0;" : "+l"(acc[2 * q + 1]) : "l"(xx), "l"(wv.y));
            }
        }
    }

    // store 64 floats = 16 STG.128
    ulonglong2* dst = (ulonglong2*)(xw + (size_t)n * OUT_DIM);
    #pragma unroll
    for (int q = 0; q < OUT_DIM / 4; q++) {
        ulonglong2 v;
        v.x = acc[2 * q];
        v.y = acc[2 * q + 1];
        dst[q] = v;
    }
}

// ---------------------------------------------------------------------------
// Scatter: out[row[e], :] += val[e] * xw[col[e], :]
// Each warp owns 32 edges: coalesced edge loads, then 16 iterations where the
// two half-warps each process one edge: lane loads float4 of xw[col], scales,
// and RED.128s (red.global.add.v4.f32) into out[row].
// ---------------------------------------------------------------------------
__global__ __launch_bounds__(256) void scatter_kernel(
    const int*   __restrict__ erow,
    const int*   __restrict__ ecol,
    const float* __restrict__ eval,
    const float* __restrict__ xw,
    float* __restrict__ out)
{
    int lane = threadIdx.x & 31;
    int warp = (blockIdx.x * 256 + threadIdx.x) >> 5;
    long base = (long)warp * 32;

    int   r = 0, c = 0;
    float v = 0.f;
    long  e = base + lane;
    if (e < N_EDGES) { r = erow[e]; c = ecol[e]; v = eval[e]; }

    int half = lane >> 4;    // which edge of the pair this half-warp handles
    int l16  = lane & 15;    // 16 lanes x float4 = 64 floats

    #pragma unroll
    for (int i = 0; i < 32; i += 2) {
        int   src = i + half;
        int   ri = __shfl_sync(0xffffffffu, r, src);
        int   ci = __shfl_sync(0xffffffffu, c, src);
        float vi = __shfl_sync(0xffffffffu, v, src);

        float4 xv = ((const float4*)(xw + (size_t)ci * OUT_DIM))[l16];
        float* dst = out + (size_t)ri * OUT_DIM + l16 * 4;
        asm volatile("red.global.add.v4.f32 [%0], {%1, %2, %3, %4};"
                     :: "l"(dst), "f"(xv.x * vi), "f"(xv.y * vi),
                        "f"(xv.z * vi), "f"(xv.w * vi)
                     : "memory");
    }
}

// ---------------------------------------------------------------------------
// ReLU in place on d_out
// ---------------------------------------------------------------------------
__global__ void relu_kernel(float4* __restrict__ out) {
    int i = blockIdx.x * blockDim.x + threadIdx.x;
    if (i < (N_NODES * OUT_DIM) / 4) {
        float4 v = out[i];
        v.x = fmaxf(v.x, 0.f);
        v.y = fmaxf(v.y, 0.f);
        v.z = fmaxf(v.z, 0.f);
        v.w = fmaxf(v.w, 0.f);
        out[i] = v;
    }
}

// ---------------------------------------------------------------------------
extern "C" void kernel_launch(void* const* d_in, const int* in_sizes, int n_in,
                              void* d_out, int out_size)
{
    const float* x    = (const float*)d_in[0];
    const int*   erow = (const int*)  d_in[1];
    const int*   ecol = (const int*)  d_in[2];
    const float* eval = (const float*)d_in[3];
    const float* W    = (const float*)d_in[4];
    const float* b    = (const float*)d_in[5];
    float*       out  = (float*)d_out;

    float* xw;
    cudaGetSymbolAddress((void**)&xw, g_xw);

    // zero d_out for the atomic accumulation
    {
        int n4 = (N_NODES * OUT_DIM) / 4;
        zero_kernel<<<(n4 + 255) / 256, 256>>>((float4*)out);
    }

    // xw = x @ W + b
    {
        int blocks = (N_NODES + 255) / 256;
        linear_kernel<<<blocks, 256>>>(x, W, b, xw);
    }

    // out += scatter-add of messages (exactly E/32 = 50000 warps)
    {
        int warps  = (N_EDGES + 31) / 32;
        int blocks = (warps + 7) / 8;       // 8 warps per 256-thread block
        scatter_kernel<<<blocks, 256>>>(erow, ecol, eval, xw, out);
    }

    // relu in place
    {
        int n4 = (N_NODES * OUT_DIM) / 4;
        relu_kernel<<<(n4 + 255) / 256, 256>>>((float4*)out);
    }
}

// round 2
// speedup vs baseline: 1.0266x; 1.0266x over previous
#include <cuda_runtime.h>
#include <cuda_bf16.h>
#include <cstdint>

#define N_NODES 100000
#define N_EDGES 1600000
#define IN_DIM  128
#define OUT_DIM 64
#define NB_SCAN ((N_NODES + 1023) / 1024)   // 98 scan blocks

// Scratch (allocation-free rule: __device__ globals)
__device__ float              g_xw[(size_t)N_NODES * OUT_DIM];    // 25.6 MB
__device__ unsigned long long g_perm[N_EDGES];                    // 12.8 MB {val,col}
__device__ int                g_off[N_NODES];                     // counts -> local excl scan -> cursors
__device__ int                g_bsum[NB_SCAN];                    // per-scan-block totals -> excl prefix

// ---------------------------------------------------------------------------
// 1) zero the per-row counters
// ---------------------------------------------------------------------------
__global__ void zero_off_kernel() {
    int i = blockIdx.x * blockDim.x + threadIdx.x;
    if (i < N_NODES) g_off[i] = 0;
}

// ---------------------------------------------------------------------------
// 2) histogram of edge_row (int atomics spread over 100k L2 lines)
// ---------------------------------------------------------------------------
__global__ __launch_bounds__(256) void hist_kernel(const int* __restrict__ erow) {
    int e = blockIdx.x * blockDim.x + threadIdx.x;
    if (e < N_EDGES) atomicAdd(&g_off[erow[e]], 1);
}

// ---------------------------------------------------------------------------
// 3a) per-block exclusive scan of counts (in place), block totals to g_bsum
// ---------------------------------------------------------------------------
__global__ __launch_bounds__(1024) void scan1_kernel() {
    __shared__ int s[1024];
    int t = threadIdx.x;
    int idx = blockIdx.x * 1024 + t;
    int v = (idx < N_NODES) ? g_off[idx] : 0;
    s[t] = v;
    __syncthreads();
    // Hillis-Steele inclusive scan
    #pragma unroll
    for (int d = 1; d < 1024; d <<= 1) {
        int add = (t >= d) ? s[t - d] : 0;
        __syncthreads();
        s[t] += add;
        __syncthreads();
    }
    if (idx < N_NODES) g_off[idx] = s[t] - v;       // exclusive within block
    if (t == 1023) g_bsum[blockIdx.x] = s[1023];    // block total
}

// ---------------------------------------------------------------------------
// 3b) exclusive scan of the 98 block totals (single block)
// ---------------------------------------------------------------------------
__global__ void scan2_kernel() {
    __shared__ int s[NB_SCAN];
    int t = threadIdx.x;
    if (t < NB_SCAN) s[t] = g_bsum[t];
    __syncthreads();
    if (t == 0) {
        int run = 0;
        for (int i = 0; i < NB_SCAN; i++) { int x = s[i]; s[i] = run; run += x; }
    }
    __syncthreads();
    if (t < NB_SCAN) g_bsum[t] = s[t];
}

// ---------------------------------------------------------------------------
// 4) permute: perm[globalpos] = {val, col}. Cursor = g_off (local) + g_bsum.
//    After this pass, g_off[r] + g_bsum[r>>10] == global END of row r's segment.
// ---------------------------------------------------------------------------
__global__ __launch_bounds__(256) void perm_kernel(
    const int* __restrict__ erow, const int* __restrict__ ecol,
    const float* __restrict__ eval)
{
    int e = blockIdx.x * blockDim.x + threadIdx.x;
    if (e >= N_EDGES) return;
    int r = erow[e];
    int pos = atomicAdd(&g_off[r], 1) + g_bsum[r >> 10];
    unsigned long long p = ((unsigned long long)(unsigned)__float_as_int(eval[e]) << 32)
                         | (unsigned)ecol[e];
    g_perm[pos] = p;
}

// ---------------------------------------------------------------------------
// Linear: xw[n,:] = x[n,:] @ W + b. One node/thread, W in smem, f32x2 FMAs.
// ---------------------------------------------------------------------------
__global__ __launch_bounds__(256) void linear_kernel(
    const float* __restrict__ x,
    const float* __restrict__ W,
    const float* __restrict__ b,
    float* __restrict__ xw)
{
    __shared__ float Ws[IN_DIM * OUT_DIM];
    __shared__ float bs[OUT_DIM];

    int tid = threadIdx.x;
    const float4* W4  = (const float4*)W;
    float4*       Ws4 = (float4*)Ws;
    #pragma unroll
    for (int i = tid; i < (IN_DIM * OUT_DIM) / 4; i += 256) Ws4[i] = W4[i];
    if (tid < OUT_DIM) bs[tid] = b[tid];
    __syncthreads();

    int n = blockIdx.x * 256 + tid;
    if (n >= N_NODES) return;

    unsigned long long acc[OUT_DIM / 2];
    #pragma unroll
    for (int p = 0; p < OUT_DIM / 2; p++) {
        asm("mov.b64 %0, {%1, %2};" : "=l"(acc[p]) : "f"(bs[2 * p]), "f"(bs[2 * p + 1]));
    }

    const float4* xr = (const float4*)(x + (size_t)n * IN_DIM);
    const ulonglong2* Ws2 = (const ulonglong2*)Ws;

    #pragma unroll 2
    for (int k4 = 0; k4 < IN_DIM / 4; k4++) {
        float4 xv = xr[k4];
        #pragma unroll
        for (int j = 0; j < 4; j++) {
            float xk = (j == 0) ? xv.x : (j == 1) ? xv.y : (j == 2) ? xv.z : xv.w;
            unsigned long long xx;
            asm("mov.b64 %0, {%1, %1};" : "=l"(xx) : "f"(xk));
            int k = k4 * 4 + j;
            const ulonglong2* wr = Ws2 + (size_t)k * (OUT_DIM / 4);
            #pragma unroll
            for (int q = 0; q < OUT_DIM / 4; q++) {
                ulonglong2 wv = wr[q];
                asm("fma.rn.f32x2 %0, %1, %2, %0;" : "+l"(acc[2 * q])     : "l"(xx), "l"(wv.x));
                asm("fma.rn.f32x2 %0, %1, %2, %0;" : "+l"(acc[2 * q + 1]) : "l"(xx), "l"(wv.y));
            }
        }
    }

    ulonglong2* dst = (ulonglong2*)(xw + (size_t)n * OUT_DIM);
    #pragma unroll
    for (int q = 0; q < OUT_DIM / 4; q++) {
        ulonglong2 v; v.x = acc[2 * q]; v.y = acc[2 * q + 1];
        dst[q] = v;
    }
}

// ---------------------------------------------------------------------------
// 5) Segment reduce: one warp per row. Two half-warps each take alternate
//    edges; lane l16 owns float4 chunk l16 of the 64-wide row. Register
//    accumulation, halves combined via shfl, single coalesced store w/ ReLU.
// ---------------------------------------------------------------------------
__global__ __launch_bounds__(256) void gather_kernel(
    const float* __restrict__ xw,
    float4* __restrict__ out)
{
    int warp = (blockIdx.x * 256 + threadIdx.x) >> 5;
    if (warp >= N_NODES) return;
    int lane = threadIdx.x & 31;
    int half = lane >> 4;
    int l16  = lane & 15;
    int row  = warp;

    int start = (row == 0) ? 0 : (g_off[row - 1] + g_bsum[(row - 1) >> 10]);
    int end   = g_off[row] + g_bsum[row >> 10];

    float4 acc = make_float4(0.f, 0.f, 0.f, 0.f);
    for (int e = start + half; e < end; e += 2) {
        unsigned long long p = __ldg(&g_perm[e]);
        int   col = (int)(unsigned)(p & 0xffffffffu);
        float val = __int_as_float((int)(p >> 32));
        float4 xv = __ldg(((const float4*)(xw + (size_t)col * OUT_DIM)) + l16);
        acc.x = fmaf(xv.x, val, acc.x);
        acc.y = fmaf(xv.y, val, acc.y);
        acc.z = fmaf(xv.z, val, acc.z);
        acc.w = fmaf(xv.w, val, acc.w);
    }

    acc.x += __shfl_xor_sync(0xffffffffu, acc.x, 16);
    acc.y += __shfl_xor_sync(0xffffffffu, acc.y, 16);
    acc.z += __shfl_xor_sync(0xffffffffu, acc.z, 16);
    acc.w += __shfl_xor_sync(0xffffffffu, acc.w, 16);

    if (half == 0) {
        acc.x = fmaxf(acc.x, 0.f);
        acc.y = fmaxf(acc.y, 0.f);
        acc.z = fmaxf(acc.z, 0.f);
        acc.w = fmaxf(acc.w, 0.f);
        out[(size_t)row * (OUT_DIM / 4) + l16] = acc;
    }
}

// ---------------------------------------------------------------------------
extern "C" void kernel_launch(void* const* d_in, const int* in_sizes, int n_in,
                              void* d_out, int out_size)
{
    const float* x    = (const float*)d_in[0];
    const int*   erow = (const int*)  d_in[1];
    const int*   ecol = (const int*)  d_in[2];
    const float* eval = (const float*)d_in[3];
    const float* W    = (const float*)d_in[4];
    const float* b    = (const float*)d_in[5];
    float*       out  = (float*)d_out;

    float* xw;
    cudaGetSymbolAddress((void**)&xw, g_xw);

    // CSR build: zero counters -> histogram -> 2-level scan -> permute edges
    zero_off_kernel<<<(N_NODES + 255) / 256, 256>>>();
    hist_kernel<<<(N_EDGES + 255) / 256, 256>>>(erow);
    scan1_kernel<<<NB_SCAN, 1024>>>();
    scan2_kernel<<<1, 128>>>();
    perm_kernel<<<(N_EDGES + 255) / 256, 256>>>(erow, ecol, eval);

    // xw = x @ W + b
    linear_kernel<<<(N_NODES + 255) / 256, 256>>>(x, W, b, xw);

    // out = relu(segment_sum) : one warp per row
    {
        int warps  = N_NODES;
        int blocks = (warps * 32 + 255) / 256;
        gather_kernel<<<blocks, 256>>>(xw, (float4*)out);
    }
}

// round 4
// speedup vs baseline: 1.0950x; 1.0667x over previous
#include <cuda_runtime.h>
#include <cuda_bf16.h>
#include <cstdint>

#define N_NODES 100000
#define N_EDGES 1600000
#define IN_DIM  128
#define OUT_DIM 64
#define NB_SCAN ((N_NODES + 1023) / 1024)   // 98 scan blocks
#define LIN_BLOCKS ((N_NODES + 255) / 256)  // 391 linear blocks
#define HIST_BLOCKS 1024
#define ROWS_PER_WARP 4

// Scratch (allocation-free rule: __device__ globals)
__device__ float              g_xw[(size_t)N_NODES * OUT_DIM];    // 25.6 MB
__device__ unsigned long long g_perm[N_EDGES];                    // 12.8 MB {val,col}
__device__ int                g_off[N_NODES];                     // counts -> local excl scan -> cursors
__device__ int                g_bsum[NB_SCAN];                    // per-scan-block totals -> excl prefix

// ---------------------------------------------------------------------------
// Fat kernel: blocks [0, LIN_BLOCKS) do xw = x@W + b ; the rest histogram
// edge_row. Independent work overlapped in one launch.
// ---------------------------------------------------------------------------
__global__ __launch_bounds__(256) void fused_linear_hist_kernel(
    const float* __restrict__ x,
    const float* __restrict__ W,
    const float* __restrict__ b,
    const int*   __restrict__ erow,
    float* __restrict__ xw)
{
    __shared__ float Ws[IN_DIM * OUT_DIM];
    __shared__ float bs[OUT_DIM];
    int tid = threadIdx.x;

    if (blockIdx.x >= LIN_BLOCKS) {
        // ---- histogram branch (grid-stride) ----
        int i0 = (blockIdx.x - LIN_BLOCKS) * 256 + tid;
        for (int e = i0; e < N_EDGES; e += HIST_BLOCKS * 256) {
            atomicAdd(&g_off[erow[e]], 1);
        }
        return;
    }

    // ---- linear branch ----
    const float4* W4  = (const float4*)W;
    float4*       Ws4 = (float4*)Ws;
    #pragma unroll
    for (int i = tid; i < (IN_DIM * OUT_DIM) / 4; i += 256) Ws4[i] = W4[i];
    if (tid < OUT_DIM) bs[tid] = b[tid];
    __syncthreads();

    int n = blockIdx.x * 256 + tid;
    if (n >= N_NODES) return;

    unsigned long long acc[OUT_DIM / 2];
    #pragma unroll
    for (int p = 0; p < OUT_DIM / 2; p++) {
        asm("mov.b64 %0, {%1, %2};" : "=l"(acc[p]) : "f"(bs[2 * p]), "f"(bs[2 * p + 1]));
    }

    const float4* xr = (const float4*)(x + (size_t)n * IN_DIM);
    const ulonglong2* Ws2 = (const ulonglong2*)Ws;

    #pragma unroll 2
    for (int k4 = 0; k4 < IN_DIM / 4; k4++) {
        float4 xv = xr[k4];
        #pragma unroll
        for (int j = 0; j < 4; j++) {
            float xk = (j == 0) ? xv.x : (j == 1) ? xv.y : (j == 2) ? xv.z : xv.w;
            unsigned long long xx;
            asm("mov.b64 %0, {%1, %1};" : "=l"(xx) : "f"(xk));
            int k = k4 * 4 + j;
            const ulonglong2* wr = Ws2 + (size_t)k * (OUT_DIM / 4);
            #pragma unroll
            for (int q = 0; q < OUT_DIM / 4; q++) {
                ulonglong2 wv = wr[q];
                asm("fma.rn.f32x2 %0, %1, %2, %0;" : "+l"(acc[2 * q])     : "l"(xx), "l"(wv.x));
                asm("fma.rn.f32x2 %0, %1, %2, %0;" : "+l"(acc[2 * q + 1]) : "l"(xx), "l"(wv.y));
            }
        }
    }

    ulonglong2* dst = (ulonglong2*)(xw + (size_t)n * OUT_DIM);
    #pragma unroll
    for (int q = 0; q < OUT_DIM / 4; q++) {
        ulonglong2 v; v.x = acc[2 * q]; v.y = acc[2 * q + 1];
        dst[q] = v;
    }
}

// ---------------------------------------------------------------------------
// scan1: per-block exclusive scan of counts (in place), block totals to g_bsum
// ---------------------------------------------------------------------------
__global__ __launch_bounds__(1024) void scan1_kernel() {
    __shared__ int s[1024];
    int t = threadIdx.x;
    int idx = blockIdx.x * 1024 + t;
    int v = (idx < N_NODES) ? g_off[idx] : 0;
    s[t] = v;
    __syncthreads();
    #pragma unroll
    for (int d = 1; d < 1024; d <<= 1) {
        int add = (t >= d) ? s[t - d] : 0;
        __syncthreads();
        s[t] += add;
        __syncthreads();
    }
    if (idx < N_NODES) g_off[idx] = s[t] - v;       // exclusive within block
    if (t == 1023) g_bsum[blockIdx.x] = s[1023];    // block total
}

// ---------------------------------------------------------------------------
// scan2: parallel exclusive scan of the 98 block totals (one block, 128 thr)
// ---------------------------------------------------------------------------
__global__ void scan2_kernel() {
    __shared__ int s[128];
    int t = threadIdx.x;
    int v = (t < NB_SCAN) ? g_bsum[t] : 0;
    s[t] = v;
    __syncthreads();
    #pragma unroll
    for (int d = 1; d < 128; d <<= 1) {
        int add = (t >= d) ? s[t - d] : 0;
        __syncthreads();
        s[t] += add;
        __syncthreads();
    }
    if (t < NB_SCAN) g_bsum[t] = s[t] - v;          // exclusive
}

// ---------------------------------------------------------------------------
// perm: scatter {val,col} into row-sorted order via per-row cursors.
// After this, g_off[r] + g_bsum[r>>10] == global END of row r's segment.
// ---------------------------------------------------------------------------
__global__ __launch_bounds__(256) void perm_kernel(
    const int* __restrict__ erow, const int* __restrict__ ecol,
    const float* __restrict__ eval)
{
    int e = blockIdx.x * blockDim.x + threadIdx.x;
    if (e >= N_EDGES) return;
    int r = erow[e];
    int pos = atomicAdd(&g_off[r], 1) + g_bsum[r >> 10];
    unsigned long long p = ((unsigned long long)(unsigned)__float_as_int(eval[e]) << 32)
                         | (unsigned)ecol[e];
    g_perm[pos] = p;
}

// ---------------------------------------------------------------------------
// Gather: 4 rows per warp. Per row: coalesced warp-wide prefetch of up to 32
// perm entries; cols/vals broadcast via shfl executed in WARP-UNIFORM control
// flow (loop induction j is uniform; only independent load+FMA is predicated).
// Lanes >= m carry p=0 (val=0, col=0) so shfl sources are always safe.
// Each half-warp takes edges j+half and j+2+half -> 4 float4 gathers in
// flight. Halves combined via shfl_xor(16); single store with fused ReLU.
// ---------------------------------------------------------------------------
__global__ __launch_bounds__(256) void gather_kernel(
    const float* __restrict__ xw,
    float4* __restrict__ out)
{
    int warp = (blockIdx.x * 256 + threadIdx.x) >> 5;
    int lane = threadIdx.x & 31;
    int half = lane >> 4;
    int l16  = lane & 15;
    int r0   = warp * ROWS_PER_WARP;
    if (r0 >= N_NODES) return;

    #pragma unroll
    for (int rr = 0; rr < ROWS_PER_WARP; rr++) {
        int row = r0 + rr;
        if (row >= N_NODES) break;

        int s = (row == 0) ? 0 : (g_off[row - 1] + g_bsum[(row - 1) >> 10]);
        int e = g_off[row] + g_bsum[row >> 10];

        float4 a0 = make_float4(0.f, 0.f, 0.f, 0.f);
        float4 a1 = make_float4(0.f, 0.f, 0.f, 0.f);

        for (int base = s; base < e; base += 32) {
            int m = e - base; if (m > 32) m = 32;   // warp-uniform
            unsigned long long p = 0;
            if (lane < m) p = __ldg(&g_perm[base + lane]);
            unsigned plo = (unsigned)p;           // col
            unsigned phi = (unsigned)(p >> 32);   // val bits

            // j is warp-uniform -> all shfls converged
            for (int j = 0; j < m; j += 4) {
                int i0 = j + half;          // <= 29+1... <= 31
                int i1 = j + 2 + half;      // <= 31
                unsigned c0 = __shfl_sync(0xffffffffu, plo, i0);
                unsigned v0 = __shfl_sync(0xffffffffu, phi, i0);
                unsigned c1 = __shfl_sync(0xffffffffu, plo, i1);
                unsigned v1 = __shfl_sync(0xffffffffu, phi, i1);
                if (i0 < m) {
                    float4 x0 = __ldg(((const float4*)(xw + (size_t)c0 * OUT_DIM)) + l16);
                    float f0 = __int_as_float((int)v0);
                    a0.x = fmaf(x0.x, f0, a0.x); a0.y = fmaf(x0.y, f0, a0.y);
                    a0.z = fmaf(x0.z, f0, a0.z); a0.w = fmaf(x0.w, f0, a0.w);
                }
                if (i1 < m) {
                    float4 x1 = __ldg(((const float4*)(xw + (size_t)c1 * OUT_DIM)) + l16);
                    float f1 = __int_as_float((int)v1);
                    a1.x = fmaf(x1.x, f1, a1.x); a1.y = fmaf(x1.y, f1, a1.y);
                    a1.z = fmaf(x1.z, f1, a1.z); a1.w = fmaf(x1.w, f1, a1.w);
                }
            }
        }

        float4 acc;
        acc.x = a0.x + a1.x; acc.y = a0.y + a1.y;
        acc.z = a0.z + a1.z; acc.w = a0.w + a1.w;
        acc.x += __shfl_xor_sync(0xffffffffu, acc.x, 16);
        acc.y += __shfl_xor_sync(0xffffffffu, acc.y, 16);
        acc.z += __shfl_xor_sync(0xffffffffu, acc.z, 16);
        acc.w += __shfl_xor_sync(0xffffffffu, acc.w, 16);

        if (half == 0) {
            acc.x = fmaxf(acc.x, 0.f);
            acc.y = fmaxf(acc.y, 0.f);
            acc.z = fmaxf(acc.z, 0.f);
            acc.w = fmaxf(acc.w, 0.f);
            out[(size_t)row * (OUT_DIM / 4) + l16] = acc;
        }
    }
}

// ---------------------------------------------------------------------------
extern "C" void kernel_launch(void* const* d_in, const int* in_sizes, int n_in,
                              void* d_out, int out_size)
{
    const float* x    = (const float*)d_in[0];
    const int*   erow = (const int*)  d_in[1];
    const int*   ecol = (const int*)  d_in[2];
    const float* eval = (const float*)d_in[3];
    const float* W    = (const float*)d_in[4];
    const float* b    = (const float*)d_in[5];
    float*       out  = (float*)d_out;

    float* xw;  cudaGetSymbolAddress((void**)&xw, g_xw);
    int*   off; cudaGetSymbolAddress((void**)&off, g_off);

    // zero per-row counters (memset node, no kernel launch)
    cudaMemsetAsync(off, 0, N_NODES * sizeof(int));

    // linear (blocks 0..390) overlapped with edge_row histogram (rest)
    fused_linear_hist_kernel<<<LIN_BLOCKS + HIST_BLOCKS, 256>>>(x, W, b, erow, xw);

    // two-level exclusive scan of counts
    scan1_kernel<<<NB_SCAN, 1024>>>();
    scan2_kernel<<<1, 128>>>();

    // permute {val,col} into row-sorted order
    perm_kernel<<<(N_EDGES + 255) / 256, 256>>>(erow, ecol, eval);

    // out = relu(segment_sum), 4 rows per warp
    {
        int warps  = (N_NODES + ROWS_PER_WARP - 1) / ROWS_PER_WARP;
        int blocks = (warps * 32 + 255) / 256;
        gather_kernel<<<blocks, 256>>>(xw, (float4*)out);
    }
}